// round 2
// baseline (speedup 1.0000x reference)
#include <cuda_runtime.h>
#include <math.h>

// Problem dims
#define Bb 2
#define Tt 1024
#define Cc 2048
#define Hh 16
#define DK 128
#define SC 1024   // cache length
#define SS 2048   // total seq (cache + new)

// GEMM tiling
#define BM 128
#define BN 128
#define BKK 16
#define TM 8
#define TN 8
#define LDS_ 132  // BM + 4 padding

#define RSQRT_DK 0.08838834764831845f  // 1/sqrt(128)

// grid size for the [2048 x 2048] GEMMs (16 x 16 tiles)
#define BT_TILES ((Bb * Tt / BM) * (Cc / BN))

// Scratch (device globals; no runtime allocation allowed)
__device__ float g_Q[(size_t)Bb * Hh * Tt * DK];        // 16 MB, [b,h,t,d], pre-scaled by 1/sqrt(dk)
__device__ float g_scores[(size_t)Bb * Hh * Tt * SC];   // 128 MB, [bh, t, s]
__device__ float g_attn[(size_t)Bb * Tt * Cc];          // 16 MB, [b,t,h,d] == [b,t,c]

// ---------------------------------------------------------------------------
// Shared GEMM core pieces. A is always row-major [rows, lda] with K contiguous.
// NT: B row-major [N, ldb] with K contiguous (y = A * B^T)
// NN: B row-major [K, ldb=BN] with N contiguous (y = A * B), BN == 128 tile
// ---------------------------------------------------------------------------

__device__ __forceinline__ void load_a_nt(const float* __restrict__ A, int lda,
                                          int k0, float* sA) {
    int tid = threadIdx.x;
#pragma unroll
    for (int r = 0; r < 2; r++) {
        int id = tid + r * 256;            // 0..511
        int row = id >> 2;                 // 0..127
        int kq = (id & 3) << 2;            // 0,4,8,12
        float4 v = *reinterpret_cast<const float4*>(A + (size_t)row * lda + k0 + kq);
        sA[(kq + 0) * LDS_ + row] = v.x;
        sA[(kq + 1) * LDS_ + row] = v.y;
        sA[(kq + 2) * LDS_ + row] = v.z;
        sA[(kq + 3) * LDS_ + row] = v.w;
    }
}

__device__ __forceinline__ void load_b_nt(const float* __restrict__ B, int ldb,
                                          int k0, float* sB) {
    int tid = threadIdx.x;
#pragma unroll
    for (int r = 0; r < 2; r++) {
        int id = tid + r * 256;
        int row = id >> 2;
        int kq = (id & 3) << 2;
        float4 v = *reinterpret_cast<const float4*>(B + (size_t)row * ldb + k0 + kq);
        sB[(kq + 0) * LDS_ + row] = v.x;
        sB[(kq + 1) * LDS_ + row] = v.y;
        sB[(kq + 2) * LDS_ + row] = v.z;
        sB[(kq + 3) * LDS_ + row] = v.w;
    }
}

// NN B tile: rows k0..k0+15 of a [K,128] row-major matrix -> sB[k][n]
__device__ __forceinline__ void load_b_nn(const float* __restrict__ B, int ldb,
                                          int k0, float* sB) {
    int tid = threadIdx.x;
#pragma unroll
    for (int r = 0; r < 2; r++) {
        int id = tid + r * 256;            // 0..511
        int krow = id >> 5;                // 0..15
        int cq = (id & 31) << 2;           // 0..124 step 4
        float4 v = *reinterpret_cast<const float4*>(B + (size_t)(k0 + krow) * ldb + cq);
        *reinterpret_cast<float4*>(&sB[krow * LDS_ + cq]) = v;
    }
}

__device__ __forceinline__ void compute_tile(const float* sA, const float* sB,
                                             float acc[TM][TN]) {
    int tx = threadIdx.x & 15;
    int ty = threadIdx.x >> 4;
#pragma unroll
    for (int k = 0; k < BKK; k++) {
        float a[TM], b[TN];
        *reinterpret_cast<float4*>(&a[0]) = *reinterpret_cast<const float4*>(&sA[k * LDS_ + ty * TM]);
        *reinterpret_cast<float4*>(&a[4]) = *reinterpret_cast<const float4*>(&sA[k * LDS_ + ty * TM + 4]);
        *reinterpret_cast<float4*>(&b[0]) = *reinterpret_cast<const float4*>(&sB[k * LDS_ + tx * TN]);
        *reinterpret_cast<float4*>(&b[4]) = *reinterpret_cast<const float4*>(&sB[k * LDS_ + tx * TN + 4]);
#pragma unroll
        for (int i = 0; i < TM; i++)
#pragma unroll
            for (int j = 0; j < TN; j++)
                acc[i][j] = fmaf(a[i], b[j], acc[i][j]);
    }
}

// ---------------------------------------------------------------------------
// Kernel 0: copy caches into output K/V slots [bh, 0:1024, :]
// ---------------------------------------------------------------------------
__global__ void copy_cache_kernel(const float4* __restrict__ ck,
                                  const float4* __restrict__ cv,
                                  float4* __restrict__ Kout,
                                  float4* __restrict__ Vout) {
    int i = blockIdx.x * blockDim.x + threadIdx.x;   // over Bb*Hh*SC*DK/4 = 1M float4
    const int total = Bb * Hh * SC * DK / 4;
    if (i < total) {
        int pos = i & 31;          // float4 within dk row (32 per row)
        int row = i >> 5;          // [bh*1024 + s]
        int s = row & (SC - 1);
        int bh = row >> 10;
        int dst = (((bh * SS) + s) << 5) + pos;
        Kout[dst] = ck[i];
        Vout[dst] = cv[i];
    }
}

// ---------------------------------------------------------------------------
// Kernel 1: fused QKV projection. y = x @ W^T, W selected by blockIdx.y.
// Q -> g_Q ([b,h,t,d], scaled by 1/sqrt(dk)); K/V -> d_out new-token slots.
// ---------------------------------------------------------------------------
__global__ __launch_bounds__(256, 2)
void qkv_kernel(const float* __restrict__ x,
                const float* __restrict__ Wq,
                const float* __restrict__ Wk,
                const float* __restrict__ Wv,
                float* __restrict__ Kout,
                float* __restrict__ Vout) {
    __shared__ float sA[BKK * LDS_];
    __shared__ float sB[BKK * LDS_];
    int proj = blockIdx.y;
    const float* W = (proj == 0) ? Wq : ((proj == 1) ? Wk : Wv);
    int mt = blockIdx.x / (Cc / BN);
    int nt = blockIdx.x % (Cc / BN);
    int m0 = mt * BM, n0 = nt * BN;

    const float* A = x + (size_t)m0 * Cc;
    const float* B = W + (size_t)n0 * Cc;

    float acc[TM][TN];
#pragma unroll
    for (int i = 0; i < TM; i++)
#pragma unroll
        for (int j = 0; j < TN; j++) acc[i][j] = 0.f;

    for (int k0 = 0; k0 < Cc; k0 += BKK) {
        load_a_nt(A, Cc, k0, sA);
        load_b_nt(B, Cc, k0, sB);
        __syncthreads();
        compute_tile(sA, sB, acc);
        __syncthreads();
    }

    int tx = threadIdx.x & 15;
    int ty = threadIdx.x >> 4;
#pragma unroll
    for (int i = 0; i < TM; i++) {
        int m = m0 + ty * TM + i;
        int b = m >> 10;          // m / T
        int t = m & (Tt - 1);
        int n_base = n0 + tx * TN;
        int h = n_base >> 7;      // / DK (8-wide chunk never crosses a head)
        int d = n_base & (DK - 1);
        if (proj == 0) {
            float* dst = &g_Q[(((size_t)(b * Hh + h) * Tt) + t) * DK + d];
            float4 v0, v1;
            v0.x = acc[i][0] * RSQRT_DK; v0.y = acc[i][1] * RSQRT_DK;
            v0.z = acc[i][2] * RSQRT_DK; v0.w = acc[i][3] * RSQRT_DK;
            v1.x = acc[i][4] * RSQRT_DK; v1.y = acc[i][5] * RSQRT_DK;
            v1.z = acc[i][6] * RSQRT_DK; v1.w = acc[i][7] * RSQRT_DK;
            *reinterpret_cast<float4*>(dst) = v0;
            *reinterpret_cast<float4*>(dst + 4) = v1;
        } else {
            float* base = (proj == 1) ? Kout : Vout;
            float* dst = &base[(((size_t)(b * Hh + h) * SS) + SC + t) * DK + d];
            float4 v0, v1;
            v0.x = acc[i][0]; v0.y = acc[i][1]; v0.z = acc[i][2]; v0.w = acc[i][3];
            v1.x = acc[i][4]; v1.y = acc[i][5]; v1.z = acc[i][6]; v1.w = acc[i][7];
            *reinterpret_cast<float4*>(dst) = v0;
            *reinterpret_cast<float4*>(dst + 4) = v1;
        }
    }
}

// ---------------------------------------------------------------------------
// Kernel 2: scores[bh, t, s] = Q[bh,t,:] . cache_k[bh,s,:]  (Q pre-scaled)
// Causal block skip: s-tile > t-tile fully masked.
// ---------------------------------------------------------------------------
__global__ __launch_bounds__(256, 2)
void scores_kernel(const float* __restrict__ cache_k) {
    if (blockIdx.y > blockIdx.x) return;   // fully-masked tile
    __shared__ float sA[BKK * LDS_];
    __shared__ float sB[BKK * LDS_];
    int bh = blockIdx.z;
    int m0 = blockIdx.x * BM;
    int n0 = blockIdx.y * BN;

    const float* A = g_Q + (size_t)bh * Tt * DK + (size_t)m0 * DK;
    const float* B = cache_k + (size_t)bh * SC * DK + (size_t)n0 * DK;

    float acc[TM][TN];
#pragma unroll
    for (int i = 0; i < TM; i++)
#pragma unroll
        for (int j = 0; j < TN; j++) acc[i][j] = 0.f;

    for (int k0 = 0; k0 < DK; k0 += BKK) {
        load_a_nt(A, DK, k0, sA);
        load_b_nt(B, DK, k0, sB);
        __syncthreads();
        compute_tile(sA, sB, acc);
        __syncthreads();
    }

    int tx = threadIdx.x & 15;
    int ty = threadIdx.x >> 4;
    float* out = g_scores + (size_t)bh * Tt * SC;
#pragma unroll
    for (int i = 0; i < TM; i++) {
        int m = m0 + ty * TM + i;
        float* dst = &out[(size_t)m * SC + n0 + tx * TN];
        float4 v0, v1;
        v0.x = acc[i][0]; v0.y = acc[i][1]; v0.z = acc[i][2]; v0.w = acc[i][3];
        v1.x = acc[i][4]; v1.y = acc[i][5]; v1.z = acc[i][6]; v1.w = acc[i][7];
        *reinterpret_cast<float4*>(dst) = v0;
        *reinterpret_cast<float4*>(dst + 4) = v1;
    }
}

// ---------------------------------------------------------------------------
// Kernel 3: row softmax over s in [0, t]; zero-fill s in (t, 1024) so PV GEMM
// needs no masking. One 256-thread block per row; row cached in registers.
// ---------------------------------------------------------------------------
__global__ __launch_bounds__(256)
void softmax_kernel() {
    __shared__ float sred[8];
    int row = blockIdx.x;               // bh*1024 + t
    int t = row & (Tt - 1);
    int len = t + 1;
    float* p = g_scores + (size_t)row * SC;
    int tid = threadIdx.x;
    int lane = tid & 31, warp = tid >> 5;

    float v[4];
    float m = -1e30f;
#pragma unroll
    for (int j = 0; j < 4; j++) {
        int idx = tid + j * 256;
        if (idx < len) { v[j] = p[idx]; m = fmaxf(m, v[j]); }
    }
#pragma unroll
    for (int o = 16; o; o >>= 1) m = fmaxf(m, __shfl_xor_sync(0xffffffffu, m, o));
    if (lane == 0) sred[warp] = m;
    __syncthreads();
    if (tid < 32) {
        float x = (lane < 8) ? sred[lane] : -1e30f;
#pragma unroll
        for (int o = 4; o; o >>= 1) x = fmaxf(x, __shfl_xor_sync(0xffffffffu, x, o));
        if (lane == 0) sred[0] = x;
    }
    __syncthreads();
    m = sred[0];
    __syncthreads();

    float sum = 0.f;
#pragma unroll
    for (int j = 0; j < 4; j++) {
        int idx = tid + j * 256;
        if (idx < len) { v[j] = __expf(v[j] - m); sum += v[j]; }
    }
#pragma unroll
    for (int o = 16; o; o >>= 1) sum += __shfl_xor_sync(0xffffffffu, sum, o);
    if (lane == 0) sred[warp] = sum;
    __syncthreads();
    if (tid < 32) {
        float x = (lane < 8) ? sred[lane] : 0.f;
#pragma unroll
        for (int o = 4; o; o >>= 1) x += __shfl_xor_sync(0xffffffffu, x, o);
        if (lane == 0) sred[0] = x;
    }
    __syncthreads();
    float inv = 1.f / sred[0];

#pragma unroll
    for (int j = 0; j < 4; j++) {
        int idx = tid + j * 256;
        p[idx] = (idx < len) ? v[j] * inv : 0.f;
    }
}

// ---------------------------------------------------------------------------
// Kernel 4: attn_out = P @ cache_v  (NN). Per-tile k limit exploits causality
// (zeroed tail means columns beyond (mt+1)*128 contribute nothing).
// Output layout [b, t, h, d] == [b, t, c] for the Wo GEMM.
// ---------------------------------------------------------------------------
__global__ __launch_bounds__(256, 2)
void pv_kernel(const float* __restrict__ cache_v) {
    __shared__ float sA[BKK * LDS_];
    __shared__ float sB[BKK * LDS_];
    int mt = blockIdx.x;
    int bh = blockIdx.y;
    int m0 = mt * BM;
    int klim = (mt + 1) * BM;           // causal k limit (multiple of BKK)

    const float* A = g_scores + (size_t)bh * Tt * SC + (size_t)m0 * SC;
    const float* B = cache_v + (size_t)bh * SC * DK;

    float acc[TM][TN];
#pragma unroll
    for (int i = 0; i < TM; i++)
#pragma unroll
        for (int j = 0; j < TN; j++) acc[i][j] = 0.f;

    for (int k0 = 0; k0 < klim; k0 += BKK) {
        load_a_nt(A, SC, k0, sA);
        load_b_nn(B, DK, k0, sB);
        __syncthreads();
        compute_tile(sA, sB, acc);
        __syncthreads();
    }

    int tx = threadIdx.x & 15;
    int ty = threadIdx.x >> 4;
    int b = bh >> 4, h = bh & (Hh - 1);
#pragma unroll
    for (int i = 0; i < TM; i++) {
        int t = m0 + ty * TM + i;
        int d = tx * TN;
        float* dst = &g_attn[(((size_t)(b * Tt + t) * Hh) + h) * DK + d];
        float4 v0, v1;
        v0.x = acc[i][0]; v0.y = acc[i][1]; v0.z = acc[i][2]; v0.w = acc[i][3];
        v1.x = acc[i][4]; v1.y = acc[i][5]; v1.z = acc[i][6]; v1.w = acc[i][7];
        *reinterpret_cast<float4*>(dst) = v0;
        *reinterpret_cast<float4*>(dst + 4) = v1;
    }
}

// ---------------------------------------------------------------------------
// Kernel 5: final = attn_out @ Wo^T  -> d_out[0 .. B*T*C)
// ---------------------------------------------------------------------------
__global__ __launch_bounds__(256, 2)
void wo_kernel(const float* __restrict__ Wo, float* __restrict__ out) {
    __shared__ float sA[BKK * LDS_];
    __shared__ float sB[BKK * LDS_];
    int mt = blockIdx.x / (Cc / BN);
    int nt = blockIdx.x % (Cc / BN);
    int m0 = mt * BM, n0 = nt * BN;

    const float* A = g_attn + (size_t)m0 * Cc;
    const float* B = Wo + (size_t)n0 * Cc;

    float acc[TM][TN];
#pragma unroll
    for (int i = 0; i < TM; i++)
#pragma unroll
        for (int j = 0; j < TN; j++) acc[i][j] = 0.f;

    for (int k0 = 0; k0 < Cc; k0 += BKK) {
        load_a_nt(A, Cc, k0, sA);
        load_b_nt(B, Cc, k0, sB);
        __syncthreads();
        compute_tile(sA, sB, acc);
        __syncthreads();
    }

    int tx = threadIdx.x & 15;
    int ty = threadIdx.x >> 4;
#pragma unroll
    for (int i = 0; i < TM; i++) {
        int m = m0 + ty * TM + i;
        float* dst = &out[(size_t)m * Cc + n0 + tx * TN];
        float4 v0, v1;
        v0.x = acc[i][0]; v0.y = acc[i][1]; v0.z = acc[i][2]; v0.w = acc[i][3];
        v1.x = acc[i][4]; v1.y = acc[i][5]; v1.z = acc[i][6]; v1.w = acc[i][7];
        *reinterpret_cast<float4*>(dst) = v0;
        *reinterpret_cast<float4*>(dst + 4) = v1;
    }
}

// ---------------------------------------------------------------------------
extern "C" void kernel_launch(void* const* d_in, const int* in_sizes, int n_in,
                              void* d_out, int out_size) {
    const float* x  = (const float*)d_in[0];
    const float* ck = (const float*)d_in[1];
    const float* cv = (const float*)d_in[2];
    const float* Wq = (const float*)d_in[3];
    const float* Wk = (const float*)d_in[4];
    const float* Wv = (const float*)d_in[5];
    const float* Wo = (const float*)d_in[6];

    float* out  = (float*)d_out;                         // [B,T,C]
    float* Kout = out + (size_t)Bb * Tt * Cc;            // [B,H,SS,DK]
    float* Vout = Kout + (size_t)Bb * Hh * SS * DK;      // [B,H,SS,DK]

    // 0) cache -> output K/V slots (independent of everything else)
    copy_cache_kernel<<<4096, 256>>>((const float4*)ck, (const float4*)cv,
                                     (float4*)Kout, (float4*)Vout);
    // 1) QKV projections (Q scaled; K/V new tokens scattered into d_out)
    qkv_kernel<<<dim3(256, 3), 256>>>(x, Wq, Wk, Wv, Kout, Vout);
    // 2) causal scores (lower-triangular block tiles only)
    scores_kernel<<<dim3(Tt / BM, SC / BN, Bb * Hh), 256>>>(ck);
    // 3) softmax with zero-fill of masked tail
    softmax_kernel<<<Bb * Hh * Tt, 256>>>();
    // 4) P @ V with causal k-limit, output in [b,t,c]
    pv_kernel<<<dim3(Tt / BM, Bb * Hh), 256>>>(cv);
    // 5) output projection
    wo_kernel<<<BT_TILES, 256>>>(Wo, out);
}

// round 4
// speedup vs baseline: 1.7641x; 1.7641x over previous
#include <cuda_runtime.h>
#include <cuda_bf16.h>
#include <math.h>
#include <stdint.h>

// Problem dims
#define Bb 2
#define Tt 1024
#define Cc 2048
#define Hh 16
#define DK 128
#define SC 1024
#define SS 2048
#define KDIM 2048
#define NMAT 4194304ull   // 2048*2048

// fp32 GEMM tiling (scores / pv)
#define BM 128
#define BN 128
#define BKK 16
#define TM 8
#define TN 8
#define LDS_ 132

#define RSQRT_DK 0.08838834764831845f

// HMMA GEMM tiling
#define MM_BK 32
#define MM_LDS_B 80                       // bytes per smem row (32 bf16 + 8 pad)
#define MM_MAT_BYTES (128 * MM_LDS_B)     // 10240
#define MM_STAGE_BYTES (4 * MM_MAT_BYTES) // 40960 (Ah, Al, Bh, Bl)
#define MM_SMEM (2 * MM_STAGE_BYTES)      // 81920
#define MM_KSTEPS (KDIM / MM_BK)          // 64

// ---------------------------------------------------------------------------
// Scratch (device globals)
// ---------------------------------------------------------------------------
__device__ float g_Q[(size_t)Bb * Hh * Tt * DK];
__device__ float g_scores[(size_t)Bb * Hh * Tt * SC];
__device__ float g_attn[(size_t)Bb * Tt * Cc];
// bf16 hi/lo: slot 0=x, 1=Wq, 2=Wk, 3=Wv, 4=Wo
__device__ __nv_bfloat16 g_bh[5 * NMAT];
__device__ __nv_bfloat16 g_bl[5 * NMAT];
__device__ __nv_bfloat16 g_ah[NMAT];
__device__ __nv_bfloat16 g_al[NMAT];

// ---------------------------------------------------------------------------
// PTX helpers (all plain-sm_103-compatible: cp.async / ldmatrix / mma.sync)
// ---------------------------------------------------------------------------
__device__ __forceinline__ uint32_t smem_u32(const void* p) {
    uint32_t a;
    asm("{ .reg .u64 t; cvta.to.shared.u64 t, %1; cvt.u32.u64 %0, t; }" : "=r"(a) : "l"(p));
    return a;
}
#define CP_ASYNC16(saddr, gaddr) \
    asm volatile("cp.async.cg.shared.global [%0], [%1], 16;" :: "r"(saddr), "l"(gaddr))
#define CP_COMMIT() asm volatile("cp.async.commit_group;" ::: "memory")
#define CP_WAIT(n)  asm volatile("cp.async.wait_group %0;" :: "n"(n) : "memory")

__device__ __forceinline__ void ldm_x4(uint32_t addr, uint32_t* r) {
    asm volatile("ldmatrix.sync.aligned.m8n8.x4.shared.b16 {%0,%1,%2,%3}, [%4];"
        : "=r"(r[0]), "=r"(r[1]), "=r"(r[2]), "=r"(r[3]) : "r"(addr));
}
__device__ __forceinline__ void ldm_x2(uint32_t addr, uint32_t* r) {
    asm volatile("ldmatrix.sync.aligned.m8n8.x2.shared.b16 {%0,%1}, [%2];"
        : "=r"(r[0]), "=r"(r[1]) : "r"(addr));
}
__device__ __forceinline__ void mma_bf16(float* d, const uint32_t* a, const uint32_t* b) {
    asm volatile("mma.sync.aligned.m16n8k16.row.col.f32.bf16.bf16.f32 "
        "{%0,%1,%2,%3}, {%4,%5,%6,%7}, {%8,%9}, {%0,%1,%2,%3};"
        : "+f"(d[0]), "+f"(d[1]), "+f"(d[2]), "+f"(d[3])
        : "r"(a[0]), "r"(a[1]), "r"(a[2]), "r"(a[3]), "r"(b[0]), "r"(b[1]));
}

// ---------------------------------------------------------------------------
// fp32 SGEMM core (scores / pv) — unchanged from the passing R2 kernel
// ---------------------------------------------------------------------------
__device__ __forceinline__ void load_a_nt(const float* __restrict__ A, int lda,
                                          int k0, float* sA) {
    int tid = threadIdx.x;
#pragma unroll
    for (int r = 0; r < 2; r++) {
        int id = tid + r * 256;
        int row = id >> 2;
        int kq = (id & 3) << 2;
        float4 v = *reinterpret_cast<const float4*>(A + (size_t)row * lda + k0 + kq);
        sA[(kq + 0) * LDS_ + row] = v.x;
        sA[(kq + 1) * LDS_ + row] = v.y;
        sA[(kq + 2) * LDS_ + row] = v.z;
        sA[(kq + 3) * LDS_ + row] = v.w;
    }
}
__device__ __forceinline__ void load_b_nn(const float* __restrict__ B, int ldb,
                                          int k0, float* sB) {
    int tid = threadIdx.x;
#pragma unroll
    for (int r = 0; r < 2; r++) {
        int id = tid + r * 256;
        int krow = id >> 5;
        int cq = (id & 31) << 2;
        float4 v = *reinterpret_cast<const float4*>(B + (size_t)(k0 + krow) * ldb + cq);
        *reinterpret_cast<float4*>(&sB[krow * LDS_ + cq]) = v;
    }
}
__device__ __forceinline__ void compute_tile(const float* sA, const float* sB,
                                             float acc[TM][TN]) {
    int tx = threadIdx.x & 15;
    int ty = threadIdx.x >> 4;
#pragma unroll
    for (int k = 0; k < BKK; k++) {
        float a[TM], b[TN];
        *reinterpret_cast<float4*>(&a[0]) = *reinterpret_cast<const float4*>(&sA[k * LDS_ + ty * TM]);
        *reinterpret_cast<float4*>(&a[4]) = *reinterpret_cast<const float4*>(&sA[k * LDS_ + ty * TM + 4]);
        *reinterpret_cast<float4*>(&b[0]) = *reinterpret_cast<const float4*>(&sB[k * LDS_ + tx * TN]);
        *reinterpret_cast<float4*>(&b[4]) = *reinterpret_cast<const float4*>(&sB[k * LDS_ + tx * TN + 4]);
#pragma unroll
        for (int i = 0; i < TM; i++)
#pragma unroll
            for (int j = 0; j < TN; j++)
                acc[i][j] = fmaf(a[i], b[j], acc[i][j]);
    }
}

// ---------------------------------------------------------------------------
// copy caches -> output K/V slots
// ---------------------------------------------------------------------------
__global__ void copy_cache_kernel(const float4* __restrict__ ck,
                                  const float4* __restrict__ cv,
                                  float4* __restrict__ Kout,
                                  float4* __restrict__ Vout) {
    int i = blockIdx.x * blockDim.x + threadIdx.x;
    const int total = Bb * Hh * SC * DK / 4;
    if (i < total) {
        int pos = i & 31;
        int row = i >> 5;
        int s = row & (SC - 1);
        int bh = row >> 10;
        int dst = (((bh * SS) + s) << 5) + pos;
        Kout[dst] = ck[i];
        Vout[dst] = cv[i];
    }
}

// ---------------------------------------------------------------------------
// fp32 -> (bf16 hi, bf16 lo)
// ---------------------------------------------------------------------------
__device__ __forceinline__ void split4(float4 v, __nv_bfloat162* dh, __nv_bfloat162* dl) {
    __nv_bfloat16 h0 = __float2bfloat16(v.x);
    __nv_bfloat16 h1 = __float2bfloat16(v.y);
    __nv_bfloat16 h2 = __float2bfloat16(v.z);
    __nv_bfloat16 h3 = __float2bfloat16(v.w);
    __nv_bfloat16 l0 = __float2bfloat16(v.x - __bfloat162float(h0));
    __nv_bfloat16 l1 = __float2bfloat16(v.y - __bfloat162float(h1));
    __nv_bfloat16 l2 = __float2bfloat16(v.z - __bfloat162float(h2));
    __nv_bfloat16 l3 = __float2bfloat16(v.w - __bfloat162float(h3));
    dh[0] = __halves2bfloat162(h0, h1);
    dh[1] = __halves2bfloat162(h2, h3);
    dl[0] = __halves2bfloat162(l0, l1);
    dl[1] = __halves2bfloat162(l2, l3);
}

__global__ void convert5_kernel(const float4* __restrict__ x,
                                const float4* __restrict__ wq,
                                const float4* __restrict__ wk,
                                const float4* __restrict__ wv,
                                const float4* __restrict__ wo) {
    int id = blockIdx.x * blockDim.x + threadIdx.x;
    const int per = (int)(NMAT / 4);
    int mat = id / per;
    int rem = id - mat * per;
    const float4* srcs[5] = {x, wq, wk, wv, wo};
    float4 v = srcs[mat][rem];
    __nv_bfloat162* dh = reinterpret_cast<__nv_bfloat162*>(g_bh + (size_t)mat * NMAT) + rem * 2;
    __nv_bfloat162* dl = reinterpret_cast<__nv_bfloat162*>(g_bl + (size_t)mat * NMAT) + rem * 2;
    split4(v, dh, dl);
}

__global__ void convert_attn_kernel() {
    int id = blockIdx.x * blockDim.x + threadIdx.x;
    float4 v = reinterpret_cast<const float4*>(g_attn)[id];
    __nv_bfloat162* dh = reinterpret_cast<__nv_bfloat162*>(g_ah) + id * 2;
    __nv_bfloat162* dl = reinterpret_cast<__nv_bfloat162*>(g_al) + id * 2;
    split4(v, dh, dl);
}

// ---------------------------------------------------------------------------
// HMMA bf16x3 GEMM: y[m,n] = sum_k A[m,k]*B[n,k] (both K-major)
// mode 0: A=x, B=W[proj]; epilogue -> g_Q / Kout / Vout
// mode 1: A=attn, B=Wo; epilogue -> out
// CTA tile 128x128x32, 8 warps (2x4), warp tile 64x32.
// ---------------------------------------------------------------------------
__global__ __launch_bounds__(256, 1)
void mm_hmma_kernel(int mode, float* __restrict__ Kout, float* __restrict__ Vout,
                    float* __restrict__ out) {
    extern __shared__ char sm[];
    const uint32_t sbu = smem_u32(sm);
    const int tid = threadIdx.x;
    const int wid = tid >> 5, lane = tid & 31;
    const int warp_m = wid >> 2;          // 0..1
    const int warp_n = wid & 3;           // 0..3

    const int proj = blockIdx.z;
    const __nv_bfloat16 *Ah, *Al, *Bh, *Bl;
    if (mode == 0) {
        Ah = g_bh;                        Al = g_bl;
        Bh = g_bh + (size_t)(1 + proj) * NMAT;
        Bl = g_bl + (size_t)(1 + proj) * NMAT;
    } else {
        Ah = g_ah;                        Al = g_al;
        Bh = g_bh + (size_t)4 * NMAT;
        Bl = g_bl + (size_t)4 * NMAT;
    }
    const int m0 = blockIdx.x * 128, n0 = blockIdx.y * 128;

    // cp.async per-thread slots: 8 x 16B chunks per stage
    const __nv_bfloat16* gptr[8];
    uint32_t soff[8];
    {
        const __nv_bfloat16* src4[4] = {
            Ah + (size_t)m0 * KDIM, Al + (size_t)m0 * KDIM,
            Bh + (size_t)n0 * KDIM, Bl + (size_t)n0 * KDIM
        };
#pragma unroll
        for (int j = 0; j < 8; j++) {
            int c = j * 256 + tid;        // 0..2047
            int mat = c >> 9;             // 0..3
            int r = (c >> 2) & 127;       // 0..127
            int c16 = c & 3;              // 0..3
            gptr[j] = src4[mat] + (size_t)r * KDIM + c16 * 8;
            soff[j] = (uint32_t)(mat * MM_MAT_BYTES + r * MM_LDS_B + c16 * 16);
        }
    }

    // ldmatrix base offsets (per thread)
    const uint32_t a_row = (uint32_t)(warp_m * 64 + (lane & 15));   // + mi*16
    const uint32_t a_kb  = (uint32_t)(((lane >> 4) << 3) * 2);      // byte col off (+kk*2)
    const uint32_t b_row = (uint32_t)(warp_n * 32 + (lane & 7));    // + ni*8
    const uint32_t b_kb  = (uint32_t)((((lane >> 3) & 1) << 3) * 2);

    float acc[4][4][4];
#pragma unroll
    for (int mi = 0; mi < 4; mi++)
#pragma unroll
        for (int ni = 0; ni < 4; ni++)
#pragma unroll
            for (int q = 0; q < 4; q++) acc[mi][ni][q] = 0.f;

    // prologue: stage 0, k=0
#pragma unroll
    for (int j = 0; j < 8; j++) CP_ASYNC16(sbu + soff[j], gptr[j]);
    CP_COMMIT();

    for (int i = 0; i < MM_KSTEPS; i++) {
        const int s = i & 1;
        if (i + 1 < MM_KSTEPS) {
            const uint32_t sb2 = sbu + ((i + 1) & 1) * MM_STAGE_BYTES;
            const int k0 = (i + 1) * MM_BK;
#pragma unroll
            for (int j = 0; j < 8; j++) CP_ASYNC16(sb2 + soff[j], gptr[j] + k0);
            CP_COMMIT();
            CP_WAIT(1);
        } else {
            CP_WAIT(0);
        }
        __syncthreads();

        const uint32_t stage = sbu + s * MM_STAGE_BYTES;
#pragma unroll
        for (int kk = 0; kk < 2; kk++) {
            const uint32_t kb = (uint32_t)(kk * 16 * 2);
            uint32_t bh_f[4][2], bl_f[4][2];
#pragma unroll
            for (int ni = 0; ni < 4; ni++) {
                uint32_t baddr = stage + 2 * MM_MAT_BYTES +
                                 (b_row + ni * 8) * MM_LDS_B + b_kb + kb;
                ldm_x2(baddr, bh_f[ni]);
                ldm_x2(baddr + MM_MAT_BYTES, bl_f[ni]);
            }
#pragma unroll
            for (int mi = 0; mi < 4; mi++) {
                uint32_t ah_f[4], al_f[4];
                uint32_t aaddr = stage + (a_row + mi * 16) * MM_LDS_B + a_kb + kb;
                ldm_x4(aaddr, ah_f);
                ldm_x4(aaddr + MM_MAT_BYTES, al_f);
#pragma unroll
                for (int ni = 0; ni < 4; ni++) {
                    mma_bf16(acc[mi][ni], ah_f, bh_f[ni]);
                    mma_bf16(acc[mi][ni], ah_f, bl_f[ni]);
                    mma_bf16(acc[mi][ni], al_f, bh_f[ni]);
                }
            }
        }
        __syncthreads();
    }

    // epilogue
    const int gid = lane >> 2, tc = lane & 3;
#pragma unroll
    for (int mi = 0; mi < 4; mi++) {
#pragma unroll
        for (int ni = 0; ni < 4; ni++) {
            int mrow0 = m0 + warp_m * 64 + mi * 16 + gid;
            int ncol  = n0 + warp_n * 32 + ni * 8 + tc * 2;
#pragma unroll
            for (int half = 0; half < 2; half++) {
                int m = mrow0 + half * 8;
                float v0 = acc[mi][ni][half * 2 + 0];
                float v1 = acc[mi][ni][half * 2 + 1];
                float* dst;
                if (mode == 0) {
                    int b = m >> 10, t = m & (Tt - 1);
                    int h = ncol >> 7, d = ncol & (DK - 1);
                    if (proj == 0) {
                        dst = g_Q + (((size_t)(b * Hh + h) * Tt) + t) * DK + d;
                        v0 *= RSQRT_DK; v1 *= RSQRT_DK;
                    } else {
                        float* base = (proj == 1) ? Kout : Vout;
                        dst = base + (((size_t)(b * Hh + h) * SS) + SC + t) * DK + d;
                    }
                } else {
                    dst = out + (size_t)m * Cc + ncol;
                }
                float2 vv; vv.x = v0; vv.y = v1;
                *reinterpret_cast<float2*>(dst) = vv;
            }
        }
    }
}

// ---------------------------------------------------------------------------
// scores (fp32, causal block skip)
// ---------------------------------------------------------------------------
__global__ __launch_bounds__(256, 2)
void scores_kernel(const float* __restrict__ cache_k) {
    if (blockIdx.y > blockIdx.x) return;
    __shared__ float sA[BKK * LDS_];
    __shared__ float sB[BKK * LDS_];
    int bh = blockIdx.z;
    int m0 = blockIdx.x * BM;
    int n0 = blockIdx.y * BN;

    const float* A = g_Q + (size_t)bh * Tt * DK + (size_t)m0 * DK;
    const float* B = cache_k + (size_t)bh * SC * DK + (size_t)n0 * DK;

    float acc[TM][TN];
#pragma unroll
    for (int i = 0; i < TM; i++)
#pragma unroll
        for (int j = 0; j < TN; j++) acc[i][j] = 0.f;

    for (int k0 = 0; k0 < DK; k0 += BKK) {
        load_a_nt(A, DK, k0, sA);
        load_a_nt(B, DK, k0, sB);
        __syncthreads();
        compute_tile(sA, sB, acc);
        __syncthreads();
    }

    int tx = threadIdx.x & 15;
    int ty = threadIdx.x >> 4;
    float* outp = g_scores + (size_t)bh * Tt * SC;
#pragma unroll
    for (int i = 0; i < TM; i++) {
        int m = m0 + ty * TM + i;
        float* dst = &outp[(size_t)m * SC + n0 + tx * TN];
        float4 v0, v1;
        v0.x = acc[i][0]; v0.y = acc[i][1]; v0.z = acc[i][2]; v0.w = acc[i][3];
        v1.x = acc[i][4]; v1.y = acc[i][5]; v1.z = acc[i][6]; v1.w = acc[i][7];
        *reinterpret_cast<float4*>(dst) = v0;
        *reinterpret_cast<float4*>(dst + 4) = v1;
    }
}

// ---------------------------------------------------------------------------
// softmax (zero-fills masked tail)
// ---------------------------------------------------------------------------
__global__ __launch_bounds__(256)
void softmax_kernel() {
    __shared__ float sred[8];
    int row = blockIdx.x;
    int t = row & (Tt - 1);
    int len = t + 1;
    float* p = g_scores + (size_t)row * SC;
    int tid = threadIdx.x;
    int lane = tid & 31, warp = tid >> 5;

    float v[4];
    float m = -1e30f;
#pragma unroll
    for (int j = 0; j < 4; j++) {
        int idx = tid + j * 256;
        if (idx < len) { v[j] = p[idx]; m = fmaxf(m, v[j]); }
    }
#pragma unroll
    for (int o = 16; o; o >>= 1) m = fmaxf(m, __shfl_xor_sync(0xffffffffu, m, o));
    if (lane == 0) sred[warp] = m;
    __syncthreads();
    if (tid < 32) {
        float x = (lane < 8) ? sred[lane] : -1e30f;
#pragma unroll
        for (int o = 4; o; o >>= 1) x = fmaxf(x, __shfl_xor_sync(0xffffffffu, x, o));
        if (lane == 0) sred[0] = x;
    }
    __syncthreads();
    m = sred[0];
    __syncthreads();

    float sum = 0.f;
#pragma unroll
    for (int j = 0; j < 4; j++) {
        int idx = tid + j * 256;
        if (idx < len) { v[j] = __expf(v[j] - m); sum += v[j]; }
    }
#pragma unroll
    for (int o = 16; o; o >>= 1) sum += __shfl_xor_sync(0xffffffffu, sum, o);
    if (lane == 0) sred[warp] = sum;
    __syncthreads();
    if (tid < 32) {
        float x = (lane < 8) ? sred[lane] : 0.f;
#pragma unroll
        for (int o = 4; o; o >>= 1) x += __shfl_xor_sync(0xffffffffu, x, o);
        if (lane == 0) sred[0] = x;
    }
    __syncthreads();
    float inv = 1.f / sred[0];

#pragma unroll
    for (int j = 0; j < 4; j++) {
        int idx = tid + j * 256;
        p[idx] = (idx < len) ? v[j] * inv : 0.f;
    }
}

// ---------------------------------------------------------------------------
// P @ V (fp32, causal k-limit)
// ---------------------------------------------------------------------------
__global__ __launch_bounds__(256, 2)
void pv_kernel(const float* __restrict__ cache_v) {
    __shared__ float sA[BKK * LDS_];
    __shared__ float sB[BKK * LDS_];
    int mt = blockIdx.x;
    int bh = blockIdx.y;
    int m0 = mt * BM;
    int klim = (mt + 1) * BM;

    const float* A = g_scores + (size_t)bh * Tt * SC + (size_t)m0 * SC;
    const float* B = cache_v + (size_t)bh * SC * DK;

    float acc[TM][TN];
#pragma unroll
    for (int i = 0; i < TM; i++)
#pragma unroll
        for (int j = 0; j < TN; j++) acc[i][j] = 0.f;

    for (int k0 = 0; k0 < klim; k0 += BKK) {
        load_a_nt(A, SC, k0, sA);
        load_b_nn(B, DK, k0, sB);
        __syncthreads();
        compute_tile(sA, sB, acc);
        __syncthreads();
    }

    int tx = threadIdx.x & 15;
    int ty = threadIdx.x >> 4;
    int b = bh >> 4, h = bh & (Hh - 1);
#pragma unroll
    for (int i = 0; i < TM; i++) {
        int t = m0 + ty * TM + i;
        int d = tx * TN;
        float* dst = &g_attn[(((size_t)(b * Tt + t) * Hh) + h) * DK + d];
        float4 v0, v1;
        v0.x = acc[i][0]; v0.y = acc[i][1]; v0.z = acc[i][2]; v0.w = acc[i][3];
        v1.x = acc[i][4]; v1.y = acc[i][5]; v1.z = acc[i][6]; v1.w = acc[i][7];
        *reinterpret_cast<float4*>(dst) = v0;
        *reinterpret_cast<float4*>(dst + 4) = v1;
    }
}

// ---------------------------------------------------------------------------
extern "C" void kernel_launch(void* const* d_in, const int* in_sizes, int n_in,
                              void* d_out, int out_size) {
    const float* x  = (const float*)d_in[0];
    const float* ck = (const float*)d_in[1];
    const float* cv = (const float*)d_in[2];
    const float* Wq = (const float*)d_in[3];
    const float* Wk = (const float*)d_in[4];
    const float* Wv = (const float*)d_in[5];
    const float* Wo = (const float*)d_in[6];

    float* out  = (float*)d_out;
    float* Kout = out + (size_t)Bb * Tt * Cc;
    float* Vout = Kout + (size_t)Bb * Hh * SS * DK;

    cudaFuncSetAttribute(mm_hmma_kernel, cudaFuncAttributeMaxDynamicSharedMemorySize, MM_SMEM);

    copy_cache_kernel<<<4096, 256>>>((const float4*)ck, (const float4*)cv,
                                     (float4*)Kout, (float4*)Vout);
    convert5_kernel<<<20480, 256>>>((const float4*)x, (const float4*)Wq,
                                    (const float4*)Wk, (const float4*)Wv,
                                    (const float4*)Wo);
    mm_hmma_kernel<<<dim3(16, 16, 3), 256, MM_SMEM>>>(0, Kout, Vout, out);
    scores_kernel<<<dim3(Tt / BM, SC / BN, Bb * Hh), 256>>>(ck);
    softmax_kernel<<<Bb * Hh * Tt, 256>>>();
    pv_kernel<<<dim3(Tt / BM, Bb * Hh), 256>>>(cv);
    convert_attn_kernel<<<4096, 256>>>();
    mm_hmma_kernel<<<dim3(16, 16, 1), 256, MM_SMEM>>>(1, Kout, Vout, out);
}

// round 5
// speedup vs baseline: 2.0781x; 1.1779x over previous
#include <cuda_runtime.h>
#include <cuda_bf16.h>
#include <math.h>
#include <stdint.h>

// Problem dims
#define Bb 2
#define Tt 1024
#define Cc 2048
#define Hh 16
#define DK 128
#define SC 1024
#define SS 2048
#define KDIM 2048
#define NMAT 4194304ull   // 2048*2048

#define RSQRT_DK 0.08838834764831845f

// HMMA GEMM tiling (128x128 CTA tile, 8 warps 2x4, warp tile 64x32, BK=32)
#define MM_BK 32
#define MM_LDS_B 80                       // bytes per smem row (32 bf16 + 16 pad)
#define MM_MAT_BYTES (128 * MM_LDS_B)     // 10240
#define MM_STAGE_BYTES (4 * MM_MAT_BYTES) // 40960
#define MM_SMEM (2 * MM_STAGE_BYTES)      // 81920
#define MM_KSTEPS (KDIM / MM_BK)          // 64
#define SC_KSTEPS (DK / MM_BK)            // 4 (scores: K = 128)

// PV tiling: A = P [128 x 32], B = V [32 x 128] (row-major k x n, ldmatrix.trans)
#define PV_LDSV 272                       // 128 bf16 (256B) + 16 pad
#define PV_MATP MM_MAT_BYTES              // 10240
#define PV_MATV (32 * PV_LDSV)            // 8704
#define PV_STAGE (2 * PV_MATP + 2 * PV_MATV)  // 37888
#define PV_SMEM (2 * PV_STAGE)            // 75776

// ---------------------------------------------------------------------------
// Scratch (device globals)
// ---------------------------------------------------------------------------
__device__ float g_scores[(size_t)Bb * Hh * Tt * SC];     // 128 MB [bh,t,s]
// bf16 hi/lo: 0=x, 1=Wq, 2=Wk, 3=Wv, 4=Wo, 5=cache_k, 6=cache_v
__device__ __nv_bfloat16 g_bh[7 * NMAT];
__device__ __nv_bfloat16 g_bl[7 * NMAT];
__device__ __nv_bfloat16 g_qh[NMAT];                      // Q [bh,t,d] scaled
__device__ __nv_bfloat16 g_ql[NMAT];
__device__ __nv_bfloat16 g_ph[(size_t)Bb * Hh * Tt * SC]; // P [bh,t,s]
__device__ __nv_bfloat16 g_pl[(size_t)Bb * Hh * Tt * SC];
__device__ __nv_bfloat16 g_ah[NMAT];                      // attn [b,t,h,d]
__device__ __nv_bfloat16 g_al[NMAT];

// ---------------------------------------------------------------------------
// PTX helpers (plain-sm_103-compatible: cp.async / ldmatrix / mma.sync)
// ---------------------------------------------------------------------------
__device__ __forceinline__ uint32_t smem_u32(const void* p) {
    uint32_t a;
    asm("{ .reg .u64 t; cvta.to.shared.u64 t, %1; cvt.u32.u64 %0, t; }" : "=r"(a) : "l"(p));
    return a;
}
#define CP_ASYNC16(saddr, gaddr) \
    asm volatile("cp.async.cg.shared.global [%0], [%1], 16;" :: "r"(saddr), "l"(gaddr))
#define CP_COMMIT() asm volatile("cp.async.commit_group;" ::: "memory")
#define CP_WAIT(n)  asm volatile("cp.async.wait_group %0;" :: "n"(n) : "memory")

__device__ __forceinline__ void ldm_x4(uint32_t addr, uint32_t* r) {
    asm volatile("ldmatrix.sync.aligned.m8n8.x4.shared.b16 {%0,%1,%2,%3}, [%4];"
        : "=r"(r[0]), "=r"(r[1]), "=r"(r[2]), "=r"(r[3]) : "r"(addr));
}
__device__ __forceinline__ void ldm_x2(uint32_t addr, uint32_t* r) {
    asm volatile("ldmatrix.sync.aligned.m8n8.x2.shared.b16 {%0,%1}, [%2];"
        : "=r"(r[0]), "=r"(r[1]) : "r"(addr));
}
__device__ __forceinline__ void ldm_x2_trans(uint32_t addr, uint32_t* r) {
    asm volatile("ldmatrix.sync.aligned.m8n8.x2.trans.shared.b16 {%0,%1}, [%2];"
        : "=r"(r[0]), "=r"(r[1]) : "r"(addr));
}
__device__ __forceinline__ void mma_bf16(float* d, const uint32_t* a, const uint32_t* b) {
    asm volatile("mma.sync.aligned.m16n8k16.row.col.f32.bf16.bf16.f32 "
        "{%0,%1,%2,%3}, {%4,%5,%6,%7}, {%8,%9}, {%0,%1,%2,%3};"
        : "+f"(d[0]), "+f"(d[1]), "+f"(d[2]), "+f"(d[3])
        : "r"(a[0]), "r"(a[1]), "r"(a[2]), "r"(a[3]), "r"(b[0]), "r"(b[1]));
}

__device__ __forceinline__ void split2_store(float v0, float v1,
                                             __nv_bfloat16* hi, __nv_bfloat16* lo) {
    __nv_bfloat16 h0 = __float2bfloat16(v0);
    __nv_bfloat16 h1 = __float2bfloat16(v1);
    __nv_bfloat16 l0 = __float2bfloat16(v0 - __bfloat162float(h0));
    __nv_bfloat16 l1 = __float2bfloat16(v1 - __bfloat162float(h1));
    *reinterpret_cast<__nv_bfloat162*>(hi) = __halves2bfloat162(h0, h1);
    *reinterpret_cast<__nv_bfloat162*>(lo) = __halves2bfloat162(l0, l1);
}

// ---------------------------------------------------------------------------
// copy caches -> output K/V slots
// ---------------------------------------------------------------------------
__global__ void copy_cache_kernel(const float4* __restrict__ ck,
                                  const float4* __restrict__ cv,
                                  float4* __restrict__ Kout,
                                  float4* __restrict__ Vout) {
    int i = blockIdx.x * blockDim.x + threadIdx.x;
    const int total = Bb * Hh * SC * DK / 4;
    if (i < total) {
        int pos = i & 31;
        int row = i >> 5;
        int s = row & (SC - 1);
        int bh = row >> 10;
        int dst = (((bh * SS) + s) << 5) + pos;
        Kout[dst] = ck[i];
        Vout[dst] = cv[i];
    }
}

// ---------------------------------------------------------------------------
// fp32 -> (bf16 hi, bf16 lo) for 7 matrices
// ---------------------------------------------------------------------------
__device__ __forceinline__ void split4(float4 v, __nv_bfloat162* dh, __nv_bfloat162* dl) {
    __nv_bfloat16 h0 = __float2bfloat16(v.x);
    __nv_bfloat16 h1 = __float2bfloat16(v.y);
    __nv_bfloat16 h2 = __float2bfloat16(v.z);
    __nv_bfloat16 h3 = __float2bfloat16(v.w);
    __nv_bfloat16 l0 = __float2bfloat16(v.x - __bfloat162float(h0));
    __nv_bfloat16 l1 = __float2bfloat16(v.y - __bfloat162float(h1));
    __nv_bfloat16 l2 = __float2bfloat16(v.z - __bfloat162float(h2));
    __nv_bfloat16 l3 = __float2bfloat16(v.w - __bfloat162float(h3));
    dh[0] = __halves2bfloat162(h0, h1);
    dh[1] = __halves2bfloat162(h2, h3);
    dl[0] = __halves2bfloat162(l0, l1);
    dl[1] = __halves2bfloat162(l2, l3);
}

__global__ void convert7_kernel(const float4* __restrict__ x,
                                const float4* __restrict__ wq,
                                const float4* __restrict__ wk,
                                const float4* __restrict__ wv,
                                const float4* __restrict__ wo,
                                const float4* __restrict__ ck,
                                const float4* __restrict__ cv) {
    int id = blockIdx.x * blockDim.x + threadIdx.x;
    const int per = (int)(NMAT / 4);
    int mat = id / per;
    int rem = id - mat * per;
    const float4* srcs[7] = {x, wq, wk, wv, wo, ck, cv};
    float4 v = srcs[mat][rem];
    __nv_bfloat162* dh = reinterpret_cast<__nv_bfloat162*>(g_bh + (size_t)mat * NMAT) + rem * 2;
    __nv_bfloat162* dl = reinterpret_cast<__nv_bfloat162*>(g_bl + (size_t)mat * NMAT) + rem * 2;
    split4(v, dh, dl);
}

// ---------------------------------------------------------------------------
// HMMA bf16x3 GEMM: y[m,n] = sum_k A[m,k]*B[n,k], K=2048
// mode 0: A=x, B=W[proj]; Q -> bf16 hi/lo (scaled), K/V -> d_out fp32
// mode 1: A=attn(bf16), B=Wo; -> out fp32
// ---------------------------------------------------------------------------
__global__ __launch_bounds__(256, 1)
void mm_hmma_kernel(int mode, float* __restrict__ Kout, float* __restrict__ Vout,
                    float* __restrict__ out) {
    extern __shared__ char sm[];
    const uint32_t sbu = smem_u32(sm);
    const int tid = threadIdx.x;
    const int wid = tid >> 5, lane = tid & 31;
    const int warp_m = wid >> 2;
    const int warp_n = wid & 3;

    const int proj = blockIdx.z;
    const __nv_bfloat16 *Ah, *Al, *Bh, *Bl;
    if (mode == 0) {
        Ah = g_bh;                        Al = g_bl;
        Bh = g_bh + (size_t)(1 + proj) * NMAT;
        Bl = g_bl + (size_t)(1 + proj) * NMAT;
    } else {
        Ah = g_ah;                        Al = g_al;
        Bh = g_bh + (size_t)4 * NMAT;
        Bl = g_bl + (size_t)4 * NMAT;
    }
    const int m0 = blockIdx.x * 128, n0 = blockIdx.y * 128;

    const __nv_bfloat16* gptr[8];
    uint32_t soff[8];
    {
        const __nv_bfloat16* src4[4] = {
            Ah + (size_t)m0 * KDIM, Al + (size_t)m0 * KDIM,
            Bh + (size_t)n0 * KDIM, Bl + (size_t)n0 * KDIM
        };
#pragma unroll
        for (int j = 0; j < 8; j++) {
            int c = j * 256 + tid;
            int mat = c >> 9;
            int r = (c >> 2) & 127;
            int c16 = c & 3;
            gptr[j] = src4[mat] + (size_t)r * KDIM + c16 * 8;
            soff[j] = (uint32_t)(mat * MM_MAT_BYTES + r * MM_LDS_B + c16 * 16);
        }
    }

    const uint32_t a_row = (uint32_t)(warp_m * 64 + (lane & 15));
    const uint32_t a_kb  = (uint32_t)(((lane >> 4) << 3) * 2);
    const uint32_t b_row = (uint32_t)(warp_n * 32 + (lane & 7));
    const uint32_t b_kb  = (uint32_t)((((lane >> 3) & 1) << 3) * 2);

    float acc[4][4][4];
#pragma unroll
    for (int mi = 0; mi < 4; mi++)
#pragma unroll
        for (int ni = 0; ni < 4; ni++)
#pragma unroll
            for (int q = 0; q < 4; q++) acc[mi][ni][q] = 0.f;

#pragma unroll
    for (int j = 0; j < 8; j++) CP_ASYNC16(sbu + soff[j], gptr[j]);
    CP_COMMIT();

    for (int i = 0; i < MM_KSTEPS; i++) {
        const int s = i & 1;
        if (i + 1 < MM_KSTEPS) {
            const uint32_t sb2 = sbu + ((i + 1) & 1) * MM_STAGE_BYTES;
            const int k0 = (i + 1) * MM_BK;
#pragma unroll
            for (int j = 0; j < 8; j++) CP_ASYNC16(sb2 + soff[j], gptr[j] + k0);
            CP_COMMIT();
            CP_WAIT(1);
        } else {
            CP_WAIT(0);
        }
        __syncthreads();

        const uint32_t stage = sbu + s * MM_STAGE_BYTES;
#pragma unroll
        for (int kk = 0; kk < 2; kk++) {
            const uint32_t kb = (uint32_t)(kk * 32);
            uint32_t bh_f[4][2], bl_f[4][2];
#pragma unroll
            for (int ni = 0; ni < 4; ni++) {
                uint32_t baddr = stage + 2 * MM_MAT_BYTES +
                                 (b_row + ni * 8) * MM_LDS_B + b_kb + kb;
                ldm_x2(baddr, bh_f[ni]);
                ldm_x2(baddr + MM_MAT_BYTES, bl_f[ni]);
            }
#pragma unroll
            for (int mi = 0; mi < 4; mi++) {
                uint32_t ah_f[4], al_f[4];
                uint32_t aaddr = stage + (a_row + mi * 16) * MM_LDS_B + a_kb + kb;
                ldm_x4(aaddr, ah_f);
                ldm_x4(aaddr + MM_MAT_BYTES, al_f);
#pragma unroll
                for (int ni = 0; ni < 4; ni++) {
                    mma_bf16(acc[mi][ni], ah_f, bh_f[ni]);
                    mma_bf16(acc[mi][ni], ah_f, bl_f[ni]);
                    mma_bf16(acc[mi][ni], al_f, bh_f[ni]);
                }
            }
        }
        __syncthreads();
    }

    const int gid = lane >> 2, tc = lane & 3;
#pragma unroll
    for (int mi = 0; mi < 4; mi++) {
#pragma unroll
        for (int ni = 0; ni < 4; ni++) {
            int mrow0 = m0 + warp_m * 64 + mi * 16 + gid;
            int ncol  = n0 + warp_n * 32 + ni * 8 + tc * 2;
#pragma unroll
            for (int half = 0; half < 2; half++) {
                int m = mrow0 + half * 8;
                float v0 = acc[mi][ni][half * 2 + 0];
                float v1 = acc[mi][ni][half * 2 + 1];
                if (mode == 0) {
                    int b = m >> 10, t = m & (Tt - 1);
                    int h = ncol >> 7, d = ncol & (DK - 1);
                    if (proj == 0) {
                        size_t qi = (((size_t)(b * Hh + h) * Tt) + t) * DK + d;
                        split2_store(v0 * RSQRT_DK, v1 * RSQRT_DK, g_qh + qi, g_ql + qi);
                    } else {
                        float* base = (proj == 1) ? Kout : Vout;
                        float* dst = base + (((size_t)(b * Hh + h) * SS) + SC + t) * DK + d;
                        float2 vv; vv.x = v0; vv.y = v1;
                        *reinterpret_cast<float2*>(dst) = vv;
                    }
                } else {
                    float* dst = out + (size_t)m * Cc + ncol;
                    float2 vv; vv.x = v0; vv.y = v1;
                    *reinterpret_cast<float2*>(dst) = vv;
                }
            }
        }
    }
}

// ---------------------------------------------------------------------------
// scores via HMMA bf16x3: scores[bh,t,s] = Q[bh,t,:] . K[bh,s,:], K-dim = 128
// causal block skip (tile col > tile row never launched into work)
// ---------------------------------------------------------------------------
__global__ __launch_bounds__(256, 1)
void scores_hmma_kernel() {
    if (blockIdx.y > blockIdx.x) return;
    extern __shared__ char sm[];
    const uint32_t sbu = smem_u32(sm);
    const int tid = threadIdx.x;
    const int wid = tid >> 5, lane = tid & 31;
    const int warp_m = wid >> 2;
    const int warp_n = wid & 3;

    const int bh = blockIdx.z;
    const int m0 = blockIdx.x * 128, n0 = blockIdx.y * 128;

    const __nv_bfloat16* gptr[8];
    uint32_t soff[8];
    {
        const __nv_bfloat16* src4[4] = {
            g_qh + (size_t)bh * Tt * DK + (size_t)m0 * DK,
            g_ql + (size_t)bh * Tt * DK + (size_t)m0 * DK,
            g_bh + (size_t)5 * NMAT + (size_t)bh * SC * DK + (size_t)n0 * DK,
            g_bl + (size_t)5 * NMAT + (size_t)bh * SC * DK + (size_t)n0 * DK
        };
#pragma unroll
        for (int j = 0; j < 8; j++) {
            int c = j * 256 + tid;
            int mat = c >> 9;
            int r = (c >> 2) & 127;
            int c16 = c & 3;
            gptr[j] = src4[mat] + (size_t)r * DK + c16 * 8;
            soff[j] = (uint32_t)(mat * MM_MAT_BYTES + r * MM_LDS_B + c16 * 16);
        }
    }

    const uint32_t a_row = (uint32_t)(warp_m * 64 + (lane & 15));
    const uint32_t a_kb  = (uint32_t)(((lane >> 4) << 3) * 2);
    const uint32_t b_row = (uint32_t)(warp_n * 32 + (lane & 7));
    const uint32_t b_kb  = (uint32_t)((((lane >> 3) & 1) << 3) * 2);

    float acc[4][4][4];
#pragma unroll
    for (int mi = 0; mi < 4; mi++)
#pragma unroll
        for (int ni = 0; ni < 4; ni++)
#pragma unroll
            for (int q = 0; q < 4; q++) acc[mi][ni][q] = 0.f;

#pragma unroll
    for (int j = 0; j < 8; j++) CP_ASYNC16(sbu + soff[j], gptr[j]);
    CP_COMMIT();

    for (int i = 0; i < SC_KSTEPS; i++) {
        const int s = i & 1;
        if (i + 1 < SC_KSTEPS) {
            const uint32_t sb2 = sbu + ((i + 1) & 1) * MM_STAGE_BYTES;
            const int k0 = (i + 1) * MM_BK;
#pragma unroll
            for (int j = 0; j < 8; j++) CP_ASYNC16(sb2 + soff[j], gptr[j] + k0);
            CP_COMMIT();
            CP_WAIT(1);
        } else {
            CP_WAIT(0);
        }
        __syncthreads();

        const uint32_t stage = sbu + s * MM_STAGE_BYTES;
#pragma unroll
        for (int kk = 0; kk < 2; kk++) {
            const uint32_t kb = (uint32_t)(kk * 32);
            uint32_t bh_f[4][2], bl_f[4][2];
#pragma unroll
            for (int ni = 0; ni < 4; ni++) {
                uint32_t baddr = stage + 2 * MM_MAT_BYTES +
                                 (b_row + ni * 8) * MM_LDS_B + b_kb + kb;
                ldm_x2(baddr, bh_f[ni]);
                ldm_x2(baddr + MM_MAT_BYTES, bl_f[ni]);
            }
#pragma unroll
            for (int mi = 0; mi < 4; mi++) {
                uint32_t ah_f[4], al_f[4];
                uint32_t aaddr = stage + (a_row + mi * 16) * MM_LDS_B + a_kb + kb;
                ldm_x4(aaddr, ah_f);
                ldm_x4(aaddr + MM_MAT_BYTES, al_f);
#pragma unroll
                for (int ni = 0; ni < 4; ni++) {
                    mma_bf16(acc[mi][ni], ah_f, bh_f[ni]);
                    mma_bf16(acc[mi][ni], ah_f, bl_f[ni]);
                    mma_bf16(acc[mi][ni], al_f, bh_f[ni]);
                }
            }
        }
        __syncthreads();
    }

    float* outp = g_scores + (size_t)bh * Tt * SC;
    const int gid = lane >> 2, tc = lane & 3;
#pragma unroll
    for (int mi = 0; mi < 4; mi++) {
#pragma unroll
        for (int ni = 0; ni < 4; ni++) {
            int mrow0 = m0 + warp_m * 64 + mi * 16 + gid;
            int ncol  = n0 + warp_n * 32 + ni * 8 + tc * 2;
#pragma unroll
            for (int half = 0; half < 2; half++) {
                int t = mrow0 + half * 8;
                float2 vv;
                vv.x = acc[mi][ni][half * 2 + 0];
                vv.y = acc[mi][ni][half * 2 + 1];
                *reinterpret_cast<float2*>(outp + (size_t)t * SC + ncol) = vv;
            }
        }
    }
}

// ---------------------------------------------------------------------------
// softmax: fp32 scores in, bf16 hi/lo P out (zero tail)
// ---------------------------------------------------------------------------
__global__ __launch_bounds__(256)
void softmax_kernel() {
    __shared__ float sred[8];
    int row = blockIdx.x;
    int t = row & (Tt - 1);
    int len = t + 1;
    const float* p = g_scores + (size_t)row * SC;
    int tid = threadIdx.x;
    int lane = tid & 31, warp = tid >> 5;

    float v[4];
    float m = -1e30f;
#pragma unroll
    for (int j = 0; j < 4; j++) {
        int idx = tid + j * 256;
        if (idx < len) { v[j] = p[idx]; m = fmaxf(m, v[j]); }
    }
#pragma unroll
    for (int o = 16; o; o >>= 1) m = fmaxf(m, __shfl_xor_sync(0xffffffffu, m, o));
    if (lane == 0) sred[warp] = m;
    __syncthreads();
    if (tid < 32) {
        float x = (lane < 8) ? sred[lane] : -1e30f;
#pragma unroll
        for (int o = 4; o; o >>= 1) x = fmaxf(x, __shfl_xor_sync(0xffffffffu, x, o));
        if (lane == 0) sred[0] = x;
    }
    __syncthreads();
    m = sred[0];
    __syncthreads();

    float sum = 0.f;
#pragma unroll
    for (int j = 0; j < 4; j++) {
        int idx = tid + j * 256;
        if (idx < len) { v[j] = __expf(v[j] - m); sum += v[j]; }
    }
#pragma unroll
    for (int o = 16; o; o >>= 1) sum += __shfl_xor_sync(0xffffffffu, sum, o);
    if (lane == 0) sred[warp] = sum;
    __syncthreads();
    if (tid < 32) {
        float x = (lane < 8) ? sred[lane] : 0.f;
#pragma unroll
        for (int o = 4; o; o >>= 1) x += __shfl_xor_sync(0xffffffffu, x, o);
        if (lane == 0) sred[0] = x;
    }
    __syncthreads();
    float inv = 1.f / sred[0];

    size_t base = (size_t)row * SC;
#pragma unroll
    for (int j = 0; j < 4; j++) {
        int idx = tid + j * 256;
        float w = (idx < len) ? v[j] * inv : 0.f;
        __nv_bfloat16 hh = __float2bfloat16(w);
        g_ph[base + idx] = hh;
        g_pl[base + idx] = __float2bfloat16(w - __bfloat162float(hh));
    }
}

// ---------------------------------------------------------------------------
// PV via HMMA bf16x3: attn[bh,t,d] = sum_s P[t,s] V[s,d]
// V kept in native [s,d]; B fragments via ldmatrix.x2.trans. Causal k-limit.
// Output written as bf16 hi/lo into g_ah/g_al ([b,t,h,d]).
// ---------------------------------------------------------------------------
__global__ __launch_bounds__(256, 1)
void pv_hmma_kernel() {
    extern __shared__ char sm[];
    const uint32_t sbu = smem_u32(sm);
    const int tid = threadIdx.x;
    const int wid = tid >> 5, lane = tid & 31;
    const int warp_m = wid >> 2;
    const int warp_n = wid & 3;

    const int mt = blockIdx.x;
    const int bh = blockIdx.y;
    const int m0 = mt * 128;
    const int ksteps = (mt + 1) * 4;      // causal: s < (mt+1)*128

    const __nv_bfloat16* Ph = g_ph + (size_t)bh * Tt * SC + (size_t)m0 * SC;
    const __nv_bfloat16* Pl = g_pl + (size_t)bh * Tt * SC + (size_t)m0 * SC;
    const __nv_bfloat16* Vh = g_bh + (size_t)6 * NMAT + (size_t)bh * SC * DK;
    const __nv_bfloat16* Vl = g_bl + (size_t)6 * NMAT + (size_t)bh * SC * DK;

    // cp.async mapping: 2048 16B-chunks per stage, 8 per thread
    // c <  1024: P chunks (mat 0/1, 128 rows x 4 chunks)
    // c >= 1024: V chunks (mat 0/1, 32 rows x 16 chunks)
    const __nv_bfloat16* gptr[8];
    int gstep[8];                          // element advance per k-step
    uint32_t soff[8];
#pragma unroll
    for (int j = 0; j < 8; j++) {
        int c = j * 256 + tid;
        if (c < 1024) {
            int mat = c >> 9;
            int idx = c & 511;
            int r = idx >> 2, c16 = idx & 3;
            gptr[j] = (mat ? Pl : Ph) + (size_t)r * SC + c16 * 8;
            gstep[j] = MM_BK;
            soff[j] = (uint32_t)(mat * PV_MATP + r * MM_LDS_B + c16 * 16);
        } else {
            int q = c - 1024;
            int mat = q >> 9;
            int idx = q & 511;
            int r = idx >> 4, c16 = idx & 15;
            gptr[j] = (mat ? Vl : Vh) + (size_t)r * DK + c16 * 8;
            gstep[j] = MM_BK * DK;
            soff[j] = (uint32_t)(2 * PV_MATP + mat * PV_MATV + r * PV_LDSV + c16 * 16);
        }
    }

    const uint32_t a_row = (uint32_t)(warp_m * 64 + (lane & 15));
    const uint32_t a_kb  = (uint32_t)(((lane >> 4) << 3) * 2);
    const uint32_t v_row = (uint32_t)(lane & 15);   // k-row within 16-block

    float acc[4][4][4];
#pragma unroll
    for (int mi = 0; mi < 4; mi++)
#pragma unroll
        for (int ni = 0; ni < 4; ni++)
#pragma unroll
            for (int q = 0; q < 4; q++) acc[mi][ni][q] = 0.f;

#pragma unroll
    for (int j = 0; j < 8; j++) CP_ASYNC16(sbu + soff[j], gptr[j]);
    CP_COMMIT();

    for (int i = 0; i < ksteps; i++) {
        const int s = i & 1;
        if (i + 1 < ksteps) {
            const uint32_t sb2 = sbu + ((i + 1) & 1) * PV_STAGE;
#pragma unroll
            for (int j = 0; j < 8; j++)
                CP_ASYNC16(sb2 + soff[j], gptr[j] + (size_t)(i + 1) * gstep[j]);
            CP_COMMIT();
            CP_WAIT(1);
        } else {
            CP_WAIT(0);
        }
        __syncthreads();

        const uint32_t stage = sbu + s * PV_STAGE;
        const uint32_t vbase = stage + 2 * PV_MATP;
#pragma unroll
        for (int kk = 0; kk < 2; kk++) {
            uint32_t bh_f[4][2], bl_f[4][2];
#pragma unroll
            for (int ni = 0; ni < 4; ni++) {
                uint32_t ncl = (uint32_t)(warp_n * 32 + ni * 8) * 2;
                uint32_t baddr = vbase + (kk * 16 + v_row) * PV_LDSV + ncl;
                ldm_x2_trans(baddr, bh_f[ni]);
                ldm_x2_trans(baddr + PV_MATV, bl_f[ni]);
            }
#pragma unroll
            for (int mi = 0; mi < 4; mi++) {
                uint32_t ah_f[4], al_f[4];
                uint32_t aaddr = stage + (a_row + mi * 16) * MM_LDS_B + a_kb + (uint32_t)(kk * 32);
                ldm_x4(aaddr, ah_f);
                ldm_x4(aaddr + PV_MATP, al_f);
#pragma unroll
                for (int ni = 0; ni < 4; ni++) {
                    mma_bf16(acc[mi][ni], ah_f, bh_f[ni]);
                    mma_bf16(acc[mi][ni], ah_f, bl_f[ni]);
                    mma_bf16(acc[mi][ni], al_f, bh_f[ni]);
                }
            }
        }
        __syncthreads();
    }

    const int b = bh >> 4, h = bh & (Hh - 1);
    const int gid = lane >> 2, tc = lane & 3;
#pragma unroll
    for (int mi = 0; mi < 4; mi++) {
#pragma unroll
        for (int ni = 0; ni < 4; ni++) {
            int mrow0 = m0 + warp_m * 64 + mi * 16 + gid;
            int d = warp_n * 32 + ni * 8 + tc * 2;
#pragma unroll
            for (int half = 0; half < 2; half++) {
                int t = mrow0 + half * 8;
                float v0 = acc[mi][ni][half * 2 + 0];
                float v1 = acc[mi][ni][half * 2 + 1];
                size_t idx = (((size_t)(b * Tt + t) * Hh) + h) * DK + d;
                split2_store(v0, v1, g_ah + idx, g_al + idx);
            }
        }
    }
}

// ---------------------------------------------------------------------------
extern "C" void kernel_launch(void* const* d_in, const int* in_sizes, int n_in,
                              void* d_out, int out_size) {
    const float* x  = (const float*)d_in[0];
    const float* ck = (const float*)d_in[1];
    const float* cv = (const float*)d_in[2];
    const float* Wq = (const float*)d_in[3];
    const float* Wk = (const float*)d_in[4];
    const float* Wv = (const float*)d_in[5];
    const float* Wo = (const float*)d_in[6];

    float* out  = (float*)d_out;
    float* Kout = out + (size_t)Bb * Tt * Cc;
    float* Vout = Kout + (size_t)Bb * Hh * SS * DK;

    cudaFuncSetAttribute(mm_hmma_kernel, cudaFuncAttributeMaxDynamicSharedMemorySize, MM_SMEM);
    cudaFuncSetAttribute(scores_hmma_kernel, cudaFuncAttributeMaxDynamicSharedMemorySize, MM_SMEM);
    cudaFuncSetAttribute(pv_hmma_kernel, cudaFuncAttributeMaxDynamicSharedMemorySize, PV_SMEM);

    copy_cache_kernel<<<4096, 256>>>((const float4*)ck, (const float4*)cv,
                                     (float4*)Kout, (float4*)Vout);
    convert7_kernel<<<28672, 256>>>((const float4*)x, (const float4*)Wq,
                                    (const float4*)Wk, (const float4*)Wv,
                                    (const float4*)Wo, (const float4*)ck,
                                    (const float4*)cv);
    mm_hmma_kernel<<<dim3(16, 16, 3), 256, MM_SMEM>>>(0, Kout, Vout, out);
    scores_hmma_kernel<<<dim3(8, 8, 32), 256, MM_SMEM>>>();
    softmax_kernel<<<Bb * Hh * Tt, 256>>>();
    pv_hmma_kernel<<<dim3(8, 32), 256, PV_SMEM>>>();
    mm_hmma_kernel<<<dim3(16, 16, 1), 256, MM_SMEM>>>(1, Kout, Vout, out);
}